// round 5
// baseline (speedup 1.0000x reference)
#include <cuda_runtime.h>

// BatchNorm over features: X[N, D], stats over axis 0 (N = samples).
// N = 131072, D = 512, fp32 in/out.
//
// Pass 1: per-column sum / sumsq partials (deterministic two-stage, no atomics)
// Stage 2: fold mean/var/gamma/beta into per-column scale+shift
// Pass 2: Y = X * scale + shift (single FMA per element)

#define NROWS 131072
#define DCOLS 512
#define DV    128            // DCOLS / 4 (float4 quads per row)
#define RB1   256            // rows per block, pass 1
#define NB1   (NROWS / RB1)  // 512 blocks in pass 1
#define RB2   128            // rows per block, pass 2
#define NB2   (NROWS / RB2)  // 1024 blocks in pass 2

// Scratch (no allocation allowed -> __device__ globals).
// Partials stored transposed: g_psum[col * NB1 + block] for coalesced stage-2 reads.
__device__ float g_psum[DCOLS * NB1];
__device__ float g_psq [DCOLS * NB1];
__device__ __align__(16) float g_scale[DCOLS];
__device__ __align__(16) float g_shift[DCOLS];

// ---------------------------------------------------------------------------
// Pass 1: each block owns RB1 consecutive rows. 512 threads = 128 column
// quads x 4 row-lanes. Each thread accumulates 4 columns over RB1/4 rows.
// ---------------------------------------------------------------------------
__global__ __launch_bounds__(512, 2)
void bn_reduce_kernel(const float4* __restrict__ Xv) {
    const int b   = blockIdx.x;
    const int tid = threadIdx.x;
    const int cq  = tid & 127;   // column quad 0..127
    const int lr  = tid >> 7;    // row lane   0..3

    float sx = 0.f, sy = 0.f, sz = 0.f, sw = 0.f;
    float qx = 0.f, qy = 0.f, qz = 0.f, qw = 0.f;

    size_t base = ((size_t)b * RB1 + (size_t)lr) * DV + (size_t)cq;
    #pragma unroll 8
    for (int r = 0; r < RB1 / 4; r++) {
        float4 x = Xv[base + (size_t)r * (4 * DV)];
        sx += x.x; sy += x.y; sz += x.z; sw += x.w;
        qx = fmaf(x.x, x.x, qx);
        qy = fmaf(x.y, x.y, qy);
        qz = fmaf(x.z, x.z, qz);
        qw = fmaf(x.w, x.w, qw);
    }

    __shared__ float4 shs[512];
    __shared__ float4 shq[512];
    shs[tid] = make_float4(sx, sy, sz, sw);
    shq[tid] = make_float4(qx, qy, qz, qw);
    __syncthreads();

    if (lr == 0) {
        float4 s = shs[cq];
        float4 q = shq[cq];
        #pragma unroll
        for (int k = 1; k < 4; k++) {
            float4 a = shs[cq + 128 * k];
            float4 c = shq[cq + 128 * k];
            s.x += a.x; s.y += a.y; s.z += a.z; s.w += a.w;
            q.x += c.x; q.y += c.y; q.z += c.z; q.w += c.w;
        }
        const int c0 = 4 * cq;
        g_psum[(size_t)(c0 + 0) * NB1 + b] = s.x;
        g_psum[(size_t)(c0 + 1) * NB1 + b] = s.y;
        g_psum[(size_t)(c0 + 2) * NB1 + b] = s.z;
        g_psum[(size_t)(c0 + 3) * NB1 + b] = s.w;
        g_psq [(size_t)(c0 + 0) * NB1 + b] = q.x;
        g_psq [(size_t)(c0 + 1) * NB1 + b] = q.y;
        g_psq [(size_t)(c0 + 2) * NB1 + b] = q.z;
        g_psq [(size_t)(c0 + 3) * NB1 + b] = q.w;
    }
}

// ---------------------------------------------------------------------------
// Stage 2: one block per column. 256 threads reduce NB1=512 partials, then
// fold stats + gamma/beta into scale/shift.
// ---------------------------------------------------------------------------
__global__ __launch_bounds__(256)
void bn_finalize_kernel(const float* __restrict__ gamma,
                        const float* __restrict__ beta,
                        float inv_n) {
    const int c = blockIdx.x;
    const int t = threadIdx.x;

    float s = g_psum[(size_t)c * NB1 + t] + g_psum[(size_t)c * NB1 + t + 256];
    float q = g_psq [(size_t)c * NB1 + t] + g_psq [(size_t)c * NB1 + t + 256];

    #pragma unroll
    for (int off = 16; off > 0; off >>= 1) {
        s += __shfl_down_sync(0xFFFFFFFFu, s, off);
        q += __shfl_down_sync(0xFFFFFFFFu, q, off);
    }

    __shared__ float ss[8];
    __shared__ float sq[8];
    const int warp = t >> 5;
    const int lane = t & 31;
    if (lane == 0) { ss[warp] = s; sq[warp] = q; }
    __syncthreads();

    if (t < 8) {
        s = ss[t];
        q = sq[t];
        #pragma unroll
        for (int off = 4; off > 0; off >>= 1) {
            s += __shfl_down_sync(0x000000FFu, s, off);
            q += __shfl_down_sync(0x000000FFu, q, off);
        }
        if (t == 0) {
            float mean = s * inv_n;
            float var  = fmaf(-mean, mean, q * inv_n);  // E[x^2] - mean^2
            float inv  = rsqrtf(var);                   // no epsilon (matches reference)
            float sc   = inv * gamma[c];
            g_scale[c] = sc;
            g_shift[c] = fmaf(-mean, sc, beta[c]);
        }
    }
}

// ---------------------------------------------------------------------------
// Pass 2: each block owns RB2 rows. Thread loads its column-quad scale/shift
// once, then streams float4 load + FMA + store.
// ---------------------------------------------------------------------------
__global__ __launch_bounds__(512, 2)
void bn_normalize_kernel(const float4* __restrict__ Xv, float4* __restrict__ Yv) {
    const int b   = blockIdx.x;
    const int tid = threadIdx.x;
    const int cq  = tid & 127;
    const int lr  = tid >> 7;

    const float4 sc = reinterpret_cast<const float4*>(g_scale)[cq];
    const float4 sh = reinterpret_cast<const float4*>(g_shift)[cq];

    size_t base = ((size_t)b * RB2 + (size_t)lr) * DV + (size_t)cq;
    #pragma unroll 8
    for (int r = 0; r < RB2 / 4; r++) {
        size_t idx = base + (size_t)r * (4 * DV);
        float4 x = Xv[idx];
        float4 y;
        y.x = fmaf(x.x, sc.x, sh.x);
        y.y = fmaf(x.y, sc.y, sh.y);
        y.z = fmaf(x.z, sc.z, sh.z);
        y.w = fmaf(x.w, sc.w, sh.w);
        Yv[idx] = y;
    }
}

// ---------------------------------------------------------------------------
extern "C" void kernel_launch(void* const* d_in, const int* in_sizes, int n_in,
                              void* d_out, int out_size) {
    const float* X     = (const float*)d_in[0];
    const float* gamma = (const float*)d_in[1];
    const float* beta  = (const float*)d_in[2];
    float*       Y     = (float*)d_out;

    bn_reduce_kernel<<<NB1, 512>>>((const float4*)X);
    bn_finalize_kernel<<<DCOLS, 256>>>(gamma, beta, 1.0f / (float)NROWS);
    bn_normalize_kernel<<<NB2, 512>>>((const float4*)X, (float4*)Y);
}